// round 2
// baseline (speedup 1.0000x reference)
#include <cuda_runtime.h>

#define D 128
#define TILE 32
#define N_NODES 100000

// Scratch for wz = z @ W.T + b  (100000 x 128 fp32 = 51.2 MB)
__device__ float g_wz[N_NODES * D];
// 1 if edge_index buffer is int64, 0 if int32 (jax silently downgrades w/o x64)
__device__ int g_idx64;

// ---------------------------------------------------------------------------
// Prologue: detect edge_index element width. For genuine int64 indices, every
// int64-interpreted sample lies in [0, N). For int32 data, an int64 read packs
// two indices (a + b*2^32) and is only < N if b == 0 (p ~ 1e-5); 64 samples
// make misdetection probability ~0. Deterministic: same input -> same flag.
// ---------------------------------------------------------------------------
__global__ void detect_idx_width(const long long* __restrict__ ei, int n64) {
    int all_valid = 1;
    const int step = n64 > 64 ? n64 / 64 : 1;
    for (int i = 0; i < 64; i++) {
        long long v = ei[(long long)(i * step) % n64];
        if (v < 0 || v >= N_NODES) { all_valid = 0; break; }
    }
    g_idx64 = all_valid;
}

// ---------------------------------------------------------------------------
// Kernel 1: wz[n][o] = sum_i z[n][i] * W[o][i] + b[o]
// Block: 256 threads, TILE=32 rows x 128 cols.
// ---------------------------------------------------------------------------
__global__ void __launch_bounds__(256) gemm_kernel(const float* __restrict__ z,
                                                   const float* __restrict__ W,
                                                   const float* __restrict__ b) {
    extern __shared__ float sh[];
    float (*Wsh)[D + 1] = (float (*)[D + 1])sh;
    float (*zsh)[D + 1] = (float (*)[D + 1])(sh + D * (D + 1));

    const int t = threadIdx.x;
    const int row0 = blockIdx.x * TILE;

    #pragma unroll 4
    for (int idx = t; idx < D * D; idx += 256)
        Wsh[idx >> 7][idx & 127] = W[idx];
    #pragma unroll 4
    for (int idx = t; idx < TILE * D; idx += 256)
        zsh[idx >> 7][idx & 127] = z[(size_t)(row0 + (idx >> 7)) * D + (idx & 127)];
    __syncthreads();

    const int c = t & 63;
    const int rbase = (t >> 6) * 8;
    const float b0 = b[c];
    const float b1 = b[c + 64];

    float acc0[8], acc1[8];
    #pragma unroll
    for (int r = 0; r < 8; r++) { acc0[r] = 0.0f; acc1[r] = 0.0f; }

    #pragma unroll 4
    for (int i = 0; i < D; i++) {
        const float w0 = Wsh[c][i];
        const float w1 = Wsh[c + 64][i];
        #pragma unroll
        for (int r = 0; r < 8; r++) {
            const float zv = zsh[rbase + r][i];
            acc0[r] = fmaf(zv, w0, acc0[r]);
            acc1[r] = fmaf(zv, w1, acc1[r]);
        }
    }

    #pragma unroll
    for (int r = 0; r < 8; r++) {
        const size_t row = (size_t)(row0 + rbase + r);
        g_wz[row * D + c]      = acc0[r] + b0;
        g_wz[row * D + c + 64] = acc1[r] + b1;
    }
}

// ---------------------------------------------------------------------------
// Kernel 2: out[e] = sigmoid( dot(z[src[e]], wz[dst[e]]) )
// One warp per edge; lane l loads float4 l of each 128-float row (512 B/row =
// 32 lanes x 16 B, fully coalesced). Uniform branch on index width.
// ---------------------------------------------------------------------------
__global__ void __launch_bounds__(256) edge_kernel(const float* __restrict__ z,
                                                   const void* __restrict__ ei_raw,
                                                   float* __restrict__ out,
                                                   int E) {
    const int e = (int)((blockIdx.x * (unsigned)blockDim.x + threadIdx.x) >> 5);
    const int lane = threadIdx.x & 31;
    if (e >= E) return;

    long long src, dst;
    if (g_idx64) {
        const long long* ei = (const long long*)ei_raw;
        src = ei[e];
        dst = ei[(long long)E + e];
    } else {
        const int* ei = (const int*)ei_raw;
        src = ei[e];
        dst = ei[E + e];
    }

    const float4* zs = (const float4*)(z + (size_t)src * D);
    const float4* wd = (const float4*)(g_wz + (size_t)dst * D);

    const float4 a = zs[lane];
    const float4 w = wd[lane];

    float v = a.x * w.x + a.y * w.y + a.z * w.z + a.w * w.w;

    #pragma unroll
    for (int off = 16; off > 0; off >>= 1)
        v += __shfl_xor_sync(0xffffffff, v, off);

    if (lane == 0)
        out[e] = 1.0f / (1.0f + __expf(-v));
}

// ---------------------------------------------------------------------------
// Launch. Inputs (metadata order): z [N*D f32], edge_index [2*E int], W, b.
// Output: [E] f32. E derived from out_size (dtype-independent).
// ---------------------------------------------------------------------------
extern "C" void kernel_launch(void* const* d_in, const int* in_sizes, int n_in,
                              void* d_out, int out_size) {
    const float* z  = (const float*)d_in[0];
    const void*  ei = d_in[1];
    const float* W  = (const float*)d_in[2];
    const float* b  = (const float*)d_in[3];
    float* out = (float*)d_out;

    const int E = out_size;                 // one output per edge
    const int n_rows = in_sizes[0] / D;     // 100000
    const int n_tiles = (n_rows + TILE - 1) / TILE;

    // #int64-interpretable words in the index buffer (>= E in either dtype)
    const int n64 = in_sizes[1] / ((in_sizes[1] / 2 == E) ? 2 : 1) / 1;
    // If buffer holds 2E int32 elems, in_sizes[1]=2E -> n64 = E (reading as
    // int64 pairs). If it holds 2E int64 elems, in_sizes[1]=2E -> n64 = 2E
    // worth of int64 reads is in_sizes[1]... keep it simple & safe:
    const int n64_safe = E;                 // always safe to read E int64 words
    detect_idx_width<<<1, 1>>>((const long long*)ei, n64_safe);

    const int smem = (D * (D + 1) + TILE * (D + 1)) * (int)sizeof(float);
    cudaFuncSetAttribute(gemm_kernel, cudaFuncAttributeMaxDynamicSharedMemorySize, smem);
    gemm_kernel<<<n_tiles, 256, smem>>>(z, W, b);

    const int edges_per_block = 256 / 32;   // 8 edges per 256-thread block
    edge_kernel<<<(E + edges_per_block - 1) / edges_per_block, 256>>>(z, ei, out, E);
}

// round 3
// speedup vs baseline: 1.3207x; 1.3207x over previous
#include <cuda_runtime.h>

#define D 128
#define TILE 32
#define N_NODES 100000
#define EPW 4   // edges per warp

// Scratch for wz = z @ W.T + b  (100000 x 128 fp32 = 51.2 MB)
__device__ float g_wz[N_NODES * D];
// 1 if edge_index buffer is int64, 0 if int32 (jax silently downgrades w/o x64)
__device__ int g_idx64;

// ---------------------------------------------------------------------------
// Kernel 1: wz[n][o] = sum_i z[n][i] * W[o][i] + b[o]
// Block: 256 threads, TILE=32 rows x 128 cols.
// Block 0 / thread 0 also detects the edge_index element width: genuine int64
// samples all lie in [0, N); int32 data read as int64 packs two indices
// (a + b*2^32) and only looks valid when the odd index is 0 (p ~ 1e-5).
// 64 samples -> misdetection probability ~0. Deterministic.
// ---------------------------------------------------------------------------
__global__ void __launch_bounds__(256) gemm_kernel(const float* __restrict__ z,
                                                   const float* __restrict__ W,
                                                   const float* __restrict__ b,
                                                   const long long* __restrict__ ei64,
                                                   int E) {
    extern __shared__ float sh[];
    float (*Wsh)[D + 1] = (float (*)[D + 1])sh;
    float (*zsh)[D + 1] = (float (*)[D + 1])(sh + D * (D + 1));

    const int t = threadIdx.x;
    const int row0 = blockIdx.x * TILE;

    if (blockIdx.x == 0 && t == 0) {
        int all_valid = 1;
        const int step = E > 64 ? E / 64 : 1;
        for (int i = 0; i < 64; i++) {
            long long v = ei64[(long long)(i * step) % E];
            if (v < 0 || v >= N_NODES) { all_valid = 0; break; }
        }
        g_idx64 = all_valid;
    }

    #pragma unroll 4
    for (int idx = t; idx < D * D; idx += 256)
        Wsh[idx >> 7][idx & 127] = W[idx];
    #pragma unroll 4
    for (int idx = t; idx < TILE * D; idx += 256)
        zsh[idx >> 7][idx & 127] = z[(size_t)(row0 + (idx >> 7)) * D + (idx & 127)];
    __syncthreads();

    const int c = t & 63;
    const int rbase = (t >> 6) * 8;
    const float b0 = b[c];
    const float b1 = b[c + 64];

    float acc0[8], acc1[8];
    #pragma unroll
    for (int r = 0; r < 8; r++) { acc0[r] = 0.0f; acc1[r] = 0.0f; }

    #pragma unroll 4
    for (int i = 0; i < D; i++) {
        const float w0 = Wsh[c][i];
        const float w1 = Wsh[c + 64][i];
        #pragma unroll
        for (int r = 0; r < 8; r++) {
            const float zv = zsh[rbase + r][i];
            acc0[r] = fmaf(zv, w0, acc0[r]);
            acc1[r] = fmaf(zv, w1, acc1[r]);
        }
    }

    #pragma unroll
    for (int r = 0; r < 8; r++) {
        const size_t row = (size_t)(row0 + rbase + r);
        g_wz[row * D + c]      = acc0[r] + b0;
        g_wz[row * D + c + 64] = acc1[r] + b1;
    }
}

// ---------------------------------------------------------------------------
// Kernel 2: out[e] = sigmoid( dot(z[src[e]], wz[dst[e]]) )
// One warp handles EPW=4 consecutive edges: 8 independent LDG.128 in flight
// per warp (4x MLP vs warp-per-edge), interleaved butterfly reductions.
// Lane l covers float4 l of each 128-float row (512 B row, fully coalesced).
// ---------------------------------------------------------------------------
__global__ void __launch_bounds__(512) edge_kernel(const float* __restrict__ z,
                                                   const void* __restrict__ ei_raw,
                                                   float* __restrict__ out,
                                                   int E) {
    const int warp = (int)((blockIdx.x * 512u + threadIdx.x) >> 5);
    const int lane = threadIdx.x & 31;
    const long long e0 = (long long)warp * EPW;
    if (e0 >= E) return;

    int src[EPW], dst[EPW];
    if (g_idx64) {
        const long long* ei = (const long long*)ei_raw;
        #pragma unroll
        for (int k = 0; k < EPW; k++) {
            long long e = e0 + k; if (e >= E) e = E - 1;
            src[k] = (int)ei[e];
            dst[k] = (int)ei[(long long)E + e];
        }
    } else {
        const int* ei = (const int*)ei_raw;
        #pragma unroll
        for (int k = 0; k < EPW; k++) {
            long long e = e0 + k; if (e >= E) e = E - 1;
            src[k] = ei[e];
            dst[k] = ei[E + e];
        }
    }

    // Issue all 8 row loads before any math (max MLP).
    float4 a[EPW], w[EPW];
    #pragma unroll
    for (int k = 0; k < EPW; k++)
        a[k] = ((const float4*)(z + (size_t)src[k] * D))[lane];
    #pragma unroll
    for (int k = 0; k < EPW; k++)
        w[k] = ((const float4*)(g_wz + (size_t)dst[k] * D))[lane];

    float v[EPW];
    #pragma unroll
    for (int k = 0; k < EPW; k++)
        v[k] = a[k].x * w[k].x + a[k].y * w[k].y + a[k].z * w[k].z + a[k].w * w[k].w;

    // Interleaved butterfly reductions: the 4 chains hide each other's latency.
    #pragma unroll
    for (int off = 16; off > 0; off >>= 1) {
        #pragma unroll
        for (int k = 0; k < EPW; k++)
            v[k] += __shfl_xor_sync(0xffffffff, v[k], off);
    }

    if (lane < EPW) {
        const float vv = (lane == 0) ? v[0] : (lane == 1) ? v[1] : (lane == 2) ? v[2] : v[3];
        const long long e = e0 + lane;
        if (e < E)
            out[e] = 1.0f / (1.0f + __expf(-vv));
    }
}

// ---------------------------------------------------------------------------
// Launch. Inputs (metadata order): z [N*D f32], edge_index [2*E int], W, b.
// Output: [E] f32. E derived from out_size (dtype-independent).
// ---------------------------------------------------------------------------
extern "C" void kernel_launch(void* const* d_in, const int* in_sizes, int n_in,
                              void* d_out, int out_size) {
    const float* z  = (const float*)d_in[0];
    const void*  ei = d_in[1];
    const float* W  = (const float*)d_in[2];
    const float* b  = (const float*)d_in[3];
    float* out = (float*)d_out;

    const int E = out_size;
    const int n_rows = in_sizes[0] / D;     // 100000
    const int n_tiles = (n_rows + TILE - 1) / TILE;

    const int smem = (D * (D + 1) + TILE * (D + 1)) * (int)sizeof(float);
    cudaFuncSetAttribute(gemm_kernel, cudaFuncAttributeMaxDynamicSharedMemorySize, smem);
    gemm_kernel<<<n_tiles, 256, smem>>>(z, W, b, (const long long*)ei, E);

    const int warps_needed = (E + EPW - 1) / EPW;
    const int blocks = (warps_needed + 15) / 16;   // 16 warps (512 thr) per block
    edge_kernel<<<blocks, 512>>>(z, ei, out, E);
}